// round 4
// baseline (speedup 1.0000x reference)
#include <cuda_runtime.h>

#define DIM 16777216

__device__ __forceinline__ float spu(float v) {
    // v >= 0 : v*v - 0.5
    // v <  0 : sigmoid(-v) - 1 = 1/(1+e^v) - 1
    float pos = fmaf(v, v, -0.5f);
    float e = __expf(v);
    float neg = __fdividef(1.0f, 1.0f + e) - 1.0f;
    return (v >= 0.0f) ? pos : neg;
}

__device__ __forceinline__ void spu_elem(const float4& xv, const float4& lv, const float4& uv,
                                         float4& ox, float4& ol, float4& ou) {
    #pragma unroll
    for (int k = 0; k < 4; k++) {
        float xs = (&xv.x)[k];
        float ls = (&lv.x)[k];
        float us = (&uv.x)[k];

        float spu_l = spu(ls);
        float spu_u = spu(us);

        float lo, uo;
        if (ls >= 0.0f) {
            lo = spu_l;
            uo = spu_u;
        } else if (us <= 0.0f) {
            lo = spu_u;
            uo = spu(spu_u);   // faithful: u' = spu(spu(u))
        } else {
            lo = -0.5f;
            uo = spu_u;
        }

        (&ox.x)[k] = spu(xs);
        (&ol.x)[k] = lo;
        (&ou.x)[k] = uo;
    }
}

// 2x float4 per thread, BLOCK-contiguous (each load instruction stays
// perfectly warp-coalesced: i0 lanes contiguous, i1 lanes contiguous).
// __launch_bounds__(256, 8) caps regs at 32 to preserve occupancy.
__global__ void __launch_bounds__(256, 8) spu_box_kernel(
    const float4* __restrict__ x,
    const float4* __restrict__ l,
    const float4* __restrict__ u,
    float4* __restrict__ out_x,
    float4* __restrict__ out_l,
    float4* __restrict__ out_u)
{
    int i0 = blockIdx.x * (blockDim.x * 2) + threadIdx.x;
    int i1 = i0 + blockDim.x;

    // Issue all 6 loads before any math — MLP=6 per thread
    float4 xv0 = __ldcs(x + i0);
    float4 lv0 = __ldcs(l + i0);
    float4 uv0 = __ldcs(u + i0);
    float4 xv1 = __ldcs(x + i1);
    float4 lv1 = __ldcs(l + i1);
    float4 uv1 = __ldcs(u + i1);

    float4 ox0, ol0, ou0;
    spu_elem(xv0, lv0, uv0, ox0, ol0, ou0);
    __stcs(out_x + i0, ox0);
    __stcs(out_l + i0, ol0);
    __stcs(out_u + i0, ou0);

    float4 ox1, ol1, ou1;
    spu_elem(xv1, lv1, uv1, ox1, ol1, ou1);
    __stcs(out_x + i1, ox1);
    __stcs(out_l + i1, ol1);
    __stcs(out_u + i1, ou1);
}

extern "C" void kernel_launch(void* const* d_in, const int* in_sizes, int n_in,
                              void* d_out, int out_size) {
    const float4* x = (const float4*)d_in[0];
    const float4* l = (const float4*)d_in[1];
    const float4* u = (const float4*)d_in[2];

    float* out = (float*)d_out;
    float4* out_x = (float4*)(out);
    float4* out_l = (float4*)(out + DIM);
    float4* out_u = (float4*)(out + 2 * DIM);

    const int n4 = DIM / 4;                 // 4194304
    int threads = 256;
    int blocks = n4 / (threads * 2);        // 8192, exact (no tail)
    spu_box_kernel<<<blocks, threads>>>(x, l, u, out_x, out_l, out_u);
}

// round 5
// speedup vs baseline: 1.0070x; 1.0070x over previous
#include <cuda_runtime.h>

#define DIM 16777216

__device__ __forceinline__ float spu(float v) {
    // v >= 0 : v*v - 0.5
    // v <  0 : sigmoid(-v) - 1 = 1/(1+e^v) - 1
    float pos = fmaf(v, v, -0.5f);
    float e = __expf(v);
    float neg = __fdividef(1.0f, 1.0f + e) - 1.0f;
    return (v >= 0.0f) ? pos : neg;
}

__global__ void __launch_bounds__(256) spu_box_kernel(
    const float4* __restrict__ x,
    const float4* __restrict__ l,
    const float4* __restrict__ u,
    float4* __restrict__ out_x,
    float4* __restrict__ out_l,
    float4* __restrict__ out_u)
{
    // Grid divides DIM/4 exactly — no tail, no bounds check.
    int i = blockIdx.x * blockDim.x + threadIdx.x;

    // Three independent loads issued back-to-back (MLP=3), perfectly coalesced.
    float4 xv = x[i];
    float4 lv = l[i];
    float4 uv = u[i];

    float4 ox, ol, ou;

    #pragma unroll
    for (int k = 0; k < 4; k++) {
        float xs = (&xv.x)[k];
        float ls = (&lv.x)[k];
        float us = (&uv.x)[k];

        float spu_l = spu(ls);
        float spu_u = spu(us);

        float lo, uo;
        if (ls >= 0.0f) {
            lo = spu_l;
            uo = spu_u;
        } else if (us <= 0.0f) {
            lo = spu_u;
            uo = spu(spu_u);   // faithful: u' = spu(spu(u))
        } else {
            lo = -0.5f;
            uo = spu_u;
        }

        (&ox.x)[k] = spu(xs);
        (&ol.x)[k] = lo;
        (&ou.x)[k] = uo;
    }

    out_x[i] = ox;
    out_l[i] = ol;
    out_u[i] = ou;
}

extern "C" void kernel_launch(void* const* d_in, const int* in_sizes, int n_in,
                              void* d_out, int out_size) {
    const float4* x = (const float4*)d_in[0];
    const float4* l = (const float4*)d_in[1];
    const float4* u = (const float4*)d_in[2];

    float* out = (float*)d_out;
    float4* out_x = (float4*)(out);
    float4* out_l = (float4*)(out + DIM);
    float4* out_u = (float4*)(out + 2 * DIM);

    const int n4 = DIM / 4;            // 4194304
    int threads = 256;
    int blocks = n4 / threads;         // 16384, exact
    spu_box_kernel<<<blocks, threads>>>(x, l, u, out_x, out_l, out_u);
}